// round 15
// baseline (speedup 1.0000x reference)
#include <cuda_runtime.h>
#include <cuda_bf16.h>
#include <cstdint>

typedef unsigned long long ull;

#define TPB  512
#define BT   64

// ---------------- activations (HW tanh, 1 MUFU each) ----------------
__device__ __forceinline__ float tanh_(float x){
    float r; asm("tanh.approx.f32 %0, %1;" : "=f"(r) : "f"(x)); return r;
}
__device__ __forceinline__ float sigm(float x){
    return fmaf(0.5f, tanh_(0.5f * x), 0.5f);
}
// bf16x2 pack: lo half = a, hi half = b
__device__ __forceinline__ unsigned bf16x2_pack(float a, float b) {
    unsigned r;
    asm("cvt.rn.satfinite.bf16x2.f32 %0, %1, %2;" : "=r"(r) : "f"(b), "f"(a));
    return r;
}
// split (a,b) into bf16x2 hi + bf16x2 lo (residual)
__device__ __forceinline__ void split2(float a, float b, unsigned& hi, unsigned& lo) {
    hi = bf16x2_pack(a, b);
    float r0 = __uint_as_float(hi << 16);
    float r1 = __uint_as_float(hi & 0xffff0000u);
    lo = bf16x2_pack(a - r0, b - r1);
}
// mma.sync m16n8k16 row.col f32.bf16.bf16.f32 (baseline PTX, sm_80+)
#define MMA_BF16(d, a0, a1, a2, a3, b0, b1) \
    asm volatile("mma.sync.aligned.m16n8k16.row.col.f32.bf16.bf16.f32 " \
        "{%0,%1,%2,%3}, {%4,%5,%6,%7}, {%8,%9}, {%0,%1,%2,%3};" \
        : "+f"((d)[0]), "+f"((d)[1]), "+f"((d)[2]), "+f"((d)[3]) \
        : "r"(a0), "r"(a1), "r"(a2), "r"(a3), "r"(b0), "r"(b1))

// ---------------- SMEM layout (float offsets) ----------------
// Phase-era: WPC, WPE, CS, PHB (4 h buffers), BIASC, BIASE
// Decoder-era: WPD (aliases WPC/WPE/CS tail), PPART/BIASD/WEMBD/BEMBD (alias PHB),
//              DHA/DHB (persistent handoff), CS read-before-clobber.
#define WPC_OFF   0        // cent packed W: 3kt x 16nt x 32 ull2 = 6144 f
#define WPE_OFF   6144     // enc  packed W: 5kt x 32nt x 32 ull2 = 20480 f
#define CS_OFF    26624    // c staging [96][64] = 6144 f
#define PHB_OFF   32768    // phase h: 4 buffers (hi0,lo0,hi1,lo1), enc max 4*2560 f
#define WPD_OFF   0        // decoder packed W: 6kt x 48nt x 32 ull2 = 36864 f
#define PPART_OFF 36864    // decoder proj partials: 2 x [64][16] float2 = 4096 f
#define BIASD_OFF 40960    // 384 f  (inside dead phase-buffer region)
#define WEMBD_OFF 41344    // 96 float2 = 192 f
#define BEMBD_OFF 41536    // 2 f
#define DHA_HI    43008    // decoder h A hi: 64*49 = 3136 f
#define DHA_LO    46144
#define DHB_HI    49280
#define DHB_LO    52416
#define BIASC_OFF 55552    // 128 f
#define BIASE_OFF 55680    // 256 f
#define SMEM_FLOATS 55936
#define SMEM_BYTES  (SMEM_FLOATS * 4)   // 223,744 B

// ---------------- phase weight packing (Whh + x-kt holding Wih) ----------------
// ull2 per (kt, ntile, lane): .x = hi pair (2 b-frag regs), .y = lo pair.
template<int H>
__device__ __forceinline__ void stage_Wphase(ulonglong2* __restrict__ Wp,
                                             const float* __restrict__ Whh,
                                             const float* __restrict__ Wih, int tid)
{
    constexpr int KT = H / 16, KTX = KT + 1, NT = (4 * H) / 8;
    for (int s = tid; s < KTX * NT * 32; s += TPB) {
        int ln = s & 31;
        int ntile = (s >> 5) % NT;
        int kt = (s >> 5) / NT;
        int n = ntile * 8 + (ln >> 2);
        int kl = (ln & 3) * 2;
        float v00, v01, v10, v11;
        if (kt < KT) {
            const float* r = Whh + n * H + kt * 16 + kl;
            v00 = r[0]; v01 = r[1]; v10 = r[8]; v11 = r[9];
        } else {
            v00 = (kl == 0) ? Wih[n * 2 + 0] : 0.0f;
            v01 = (kl == 0) ? Wih[n * 2 + 1] : 0.0f;
            v10 = 0.0f; v11 = 0.0f;
        }
        unsigned h0, l0, h1, l1;
        split2(v00, v01, h0, l0);
        split2(v10, v11, h1, l1);
        ulonglong2 w;
        w.x = (ull)h0 | ((ull)h1 << 32);
        w.y = (ull)l0 | ((ull)l1 << 32);
        Wp[(kt * NT + ntile) * 32 + ln] = w;
    }
}

// ---------------- one input-driven LSTM phase via mma.sync ----------------
// Double-buffered h (hi/lo) incl. the x K-tile word -> ONE barrier per step.
template<int H, int T>
__device__ __forceinline__ void phase_mma(float* __restrict__ S,
                                          const float* __restrict__ xsrc, int xstride,
                                          int B, int bbase, int tid,
                                          int wpkOff, int biasOff,
                                          int csHOFF, int dstWordOff)
{
    constexpr int KT  = H / 16;
    constexpr int KTX = KT + 1;
    constexpr int NT  = (4 * H) / 8;
    constexpr int NTG = H / 32;          // j-ntiles per gate per warp
    constexpr int STR = H / 2 + 8;       // words per row (h words + x kt block)
    constexpr int BUFW = 64 * STR;

    int w = tid >> 5, lane = tid & 31;
    int mt = w & 3, wg = w >> 2;
    int lq = lane >> 2, lr = lane & 3;
    int brow = mt * 16 + lq;

    unsigned* P = (unsigned*)(S + PHB_OFF);   // [hi0][lo0][hi1][lo1]
    const ulonglong2* Wp = (const ulonglong2*)(S + wpkOff);
    const float* biasPh = S + biasOff;

    // zero all 4 buffers (h words start 0; x-kt pad words stay 0 forever)
    for (int s = tid; s < 4 * BUFW; s += TPB) P[s] = 0u;

    float bR[4][NTG][2];
    #pragma unroll
    for (int G = 0; G < 4; G++)
        #pragma unroll
        for (int nt = 0; nt < NTG; nt++) {
            int j = (wg * NTG + nt) * 8 + lr * 2;
            bR[G][nt][0] = biasPh[G * H + j];
            bR[G][nt][1] = biasPh[G * H + j + 1];
        }

    float c[NTG][4];
    #pragma unroll
    for (int nt = 0; nt < NTG; nt++)
        #pragma unroll
        for (int e = 0; e < 4; e++) c[nt][e] = 0.0f;

    int bx = bbase + tid; if (bx >= B) bx = B - 1;
    __syncthreads();                        // zeros done
    if (tid < 64) {                         // stage x(0) into buffer 0
        float2 x = *(const float2*)&xsrc[(size_t)bx * xstride];
        unsigned xh, xl; split2(x.x, x.y, xh, xl);
        P[tid * STR + KT * 8] = xh;              // hi0
        P[BUFW + tid * STR + KT * 8] = xl;       // lo0
    }
    __syncthreads();

    unsigned* HhiC = P;              unsigned* HloC = P + BUFW;
    unsigned* HhiN = P + 2 * BUFW;   unsigned* HloN = P + 3 * BUFW;

    int abase = brow * STR + lr;

    for (int t = 0; t < T; t++) {
        float2 xn;
        bool st = (tid < 64) && (t + 1 < T);
        if (st)
            xn = *(const float2*)&xsrc[(size_t)bx * xstride + (size_t)(t + 1) * 2];

        float acc[4 * NTG][4];
        #pragma unroll
        for (int q = 0; q < 4 * NTG; q++)
            #pragma unroll
            for (int e = 0; e < 4; e++) acc[q][e] = 0.0f;

        #pragma unroll
        for (int kt = 0; kt < KTX; kt++) {
            unsigned ah0 = HhiC[abase + kt * 8];
            unsigned ah1 = HhiC[abase + kt * 8 + 8 * STR];
            unsigned ah2 = HhiC[abase + kt * 8 + 4];
            unsigned ah3 = HhiC[abase + kt * 8 + 8 * STR + 4];
            unsigned al0 = HloC[abase + kt * 8];
            unsigned al1 = HloC[abase + kt * 8 + 8 * STR];
            unsigned al2 = HloC[abase + kt * 8 + 4];
            unsigned al3 = HloC[abase + kt * 8 + 8 * STR + 4];
            #pragma unroll
            for (int G = 0; G < 4; G++)
                #pragma unroll
                for (int nt = 0; nt < NTG; nt++) {
                    int ntile = G * (H / 8) + wg * NTG + nt;
                    ulonglong2 wv = Wp[(kt * NT + ntile) * 32 + lane];  // LDS.128
                    unsigned w0 = (unsigned)wv.x, w1 = (unsigned)(wv.x >> 32);
                    unsigned q0 = (unsigned)wv.y, q1 = (unsigned)(wv.y >> 32);
                    MMA_BF16(acc[G * NTG + nt], ah0, ah1, ah2, ah3, w0, w1);
                    MMA_BF16(acc[G * NTG + nt], al0, al1, al2, al3, w0, w1);
                    MMA_BF16(acc[G * NTG + nt], ah0, ah1, ah2, ah3, q0, q1);
                }
        }

        // epilogue -> writes go to the NEXT buffer (no read/write hazard)
        #pragma unroll
        for (int nt = 0; nt < NTG; nt++) {
            float h[4];
            #pragma unroll
            for (int idx = 0; idx < 4; idx++) {
                int p = idx & 1;
                float gi = acc[0 * NTG + nt][idx] + bR[0][nt][p];
                float gf = acc[1 * NTG + nt][idx] + bR[1][nt][p];
                float gg = acc[2 * NTG + nt][idx] + bR[2][nt][p];
                float go = acc[3 * NTG + nt][idx] + bR[3][nt][p];
                float fi = sigm(gi);
                float ff = sigm(gf);
                float fg = tanh_(gg);
                float fo = sigm(go);
                float cn = fmaf(ff, c[nt][idx], fi * fg);
                c[nt][idx] = cn;
                h[idx] = fo * tanh_(cn);
            }
            int jw = (wg * NTG + nt) * 4 + lr;
            unsigned ph0, pl0, ph1, pl1;
            split2(h[0], h[1], ph0, pl0);
            split2(h[2], h[3], ph1, pl1);
            HhiN[brow * STR + jw] = ph0;        HloN[brow * STR + jw] = pl0;
            HhiN[(brow + 8) * STR + jw] = ph1;  HloN[(brow + 8) * STR + jw] = pl1;
        }
        if (st) {
            unsigned xh, xl; split2(xn.x, xn.y, xh, xl);
            HhiN[tid * STR + KT * 8] = xh;
            HloN[tid * STR + KT * 8] = xl;
        }
        __syncthreads();                   // ONE barrier per step
        { unsigned* tp = HhiC; HhiC = HhiN; HhiN = tp; }
        { unsigned* tp = HloC; HloC = HloN; HloN = tp; }
    }
    // T even -> final h in buffer 0 (== P)

    // stage final c into Cs
    #pragma unroll
    for (int nt = 0; nt < NTG; nt++)
        #pragma unroll
        for (int idx = 0; idx < 4; idx++) {
            int j = (wg * NTG + nt) * 8 + lr * 2 + (idx & 1);
            int b = brow + (idx >> 1) * 8;
            S[CS_OFF + (csHOFF + j) * 64 + b] = c[nt][idx];
        }

    // copy final h into decoder A buffer
    constexpr int CW = 64 * (H / 2);
    unsigned* DHhi = (unsigned*)(S + DHA_HI);
    unsigned* DHlo = (unsigned*)(S + DHA_LO);
    for (int idx = tid; idx < CW; idx += TPB) {
        int row = idx / (H / 2), ww = idx % (H / 2);
        DHhi[row * 49 + dstWordOff + ww] = P[row * STR + ww];
        DHlo[row * 49 + dstWordOff + ww] = P[BUFW + row * STR + ww];
    }
}

// ---------------- main fused kernel ----------------
__global__ void __launch_bounds__(TPB, 1)
lstm_fused_kernel(const float* __restrict__ traj,   // [B,20,2]
                  const float* __restrict__ cl,     // [B,100,2]
                  const float* __restrict__ Wih_c, const float* __restrict__ Whh_c,
                  const float* __restrict__ bih_c, const float* __restrict__ bhh_c,
                  const float* __restrict__ Wih_e, const float* __restrict__ Whh_e,
                  const float* __restrict__ bih_e, const float* __restrict__ bhh_e,
                  const float* __restrict__ Wih_d, const float* __restrict__ Whh_d,
                  const float* __restrict__ bih_d, const float* __restrict__ bhh_d,
                  const float* __restrict__ W_emb, const float* __restrict__ b_emb,
                  float* __restrict__ out, int B)
{
    extern __shared__ float S[];
    int tid   = threadIdx.x;
    int bbase = blockIdx.x * BT;

    // ---- stage phase weights / biases ----
    stage_Wphase<32>((ulonglong2*)(S + WPC_OFF), Whh_c, Wih_c, tid);
    stage_Wphase<64>((ulonglong2*)(S + WPE_OFF), Whh_e, Wih_e, tid);
    for (int j = tid; j < 128; j += TPB) S[BIASC_OFF + j] = bih_c[j] + bhh_c[j];
    for (int j = tid; j < 256; j += TPB) S[BIASE_OFF + j] = bih_e[j] + bhh_e[j];
    __syncthreads();

    // ---- phase 1: centerline LSTM (H=32, 100 steps) -> dec words 32..47, c rows 64..95
    phase_mma<32, 100>(S, cl, 200, B, bbase, tid, WPC_OFF, BIASC_OFF, 64, 32);
    __syncthreads();

    // ---- phase 2: encoder LSTM (H=64, 20 steps) -> dec words 0..31, c rows 0..63
    phase_mma<64, 20>(S, traj, 40, B, bbase, tid, WPE_OFF, BIASE_OFF, 0, 0);
    __syncthreads();

    // ================= decoder via mma.sync (split-bf16) =====================
    {
        int w    = tid >> 5, lane = tid & 31;
        int mt   = w & 3;
        int wg   = w >> 2;
        int lq   = lane >> 2;
        int lr   = lane & 3;
        int brow = mt * 16 + lq;
        int jb   = wg * 24 + lr * 2;

        // read c (D-frag layout) BEFORE decoder W staging clobbers Cs
        float c[3][4];
        #pragma unroll
        for (int nt = 0; nt < 3; nt++)
            #pragma unroll
            for (int idx = 0; idx < 4; idx++) {
                int j = jb + nt * 8 + (idx & 1);
                int b = brow + (idx >> 1) * 8;
                c[nt][idx] = S[CS_OFF + j * 64 + b];
            }
        __syncthreads();

        // stage frag-packed decoder W (ull2: hi,lo), bias, Wemb
        ulonglong2* Wp = (ulonglong2*)(S + WPD_OFF);
        for (int s = tid; s < 6 * 48 * 32; s += TPB) {
            int ln = s & 31;
            int ntile = (s >> 5) % 48;
            int kt = (s >> 5) / 48;
            int n  = ntile * 8 + (ln >> 2);
            int k0 = kt * 16 + (ln & 3) * 2;
            const float* wi = Wih_d + n * 96;
            const float* wh = Whh_d + n * 96;
            float v00 = wi[k0]     + wh[k0];
            float v01 = wi[k0 + 1] + wh[k0 + 1];
            float v10 = wi[k0 + 8] + wh[k0 + 8];
            float v11 = wi[k0 + 9] + wh[k0 + 9];
            unsigned h0, l0, h1, l1;
            split2(v00, v01, h0, l0);
            split2(v10, v11, h1, l1);
            ulonglong2 wv;
            wv.x = (ull)h0 | ((ull)h1 << 32);
            wv.y = (ull)l0 | ((ull)l1 << 32);
            Wp[(kt * 48 + ntile) * 32 + ln] = wv;
        }
        float* biasd = S + BIASD_OFF;
        for (int j = tid; j < 384; j += TPB) biasd[j] = bih_d[j] + bhh_d[j];
        float2* Wemb = (float2*)(S + WEMBD_OFF);
        for (int k = tid; k < 96; k += TPB) Wemb[k] = make_float2(W_emb[k], W_emb[96 + k]);
        float2* Bemb = (float2*)(S + BEMBD_OFF);
        if (tid == 0) *Bemb = make_float2(b_emb[0], b_emb[1]);
        __syncthreads();

        unsigned* HhiC = (unsigned*)(S + DHA_HI);
        unsigned* HloC = (unsigned*)(S + DHA_LO);
        unsigned* HhiN = (unsigned*)(S + DHB_HI);
        unsigned* HloN = (unsigned*)(S + DHB_LO);
        float2* Ppart = (float2*)(S + PPART_OFF);   // [2 par][64 b][16 slot]
        int slot = wg * 4 + lr;
        int abase = brow * 49 + lr;

        for (int t = 0; t < 30; t++) {
            float acc[12][4];
            #pragma unroll
            for (int q = 0; q < 12; q++)
                #pragma unroll
                for (int e = 0; e < 4; e++) acc[q][e] = 0.0f;

            #pragma unroll
            for (int kt = 0; kt < 6; kt++) {
                unsigned ah0 = HhiC[abase + kt * 8];
                unsigned ah1 = HhiC[abase + kt * 8 + 392];
                unsigned ah2 = HhiC[abase + kt * 8 + 4];
                unsigned ah3 = HhiC[abase + kt * 8 + 396];
                unsigned al0 = HloC[abase + kt * 8];
                unsigned al1 = HloC[abase + kt * 8 + 392];
                unsigned al2 = HloC[abase + kt * 8 + 4];
                unsigned al3 = HloC[abase + kt * 8 + 396];
                #pragma unroll
                for (int G = 0; G < 4; G++)
                    #pragma unroll
                    for (int nt = 0; nt < 3; nt++) {
                        int ntile = G * 12 + wg * 3 + nt;
                        ulonglong2 wv = Wp[(kt * 48 + ntile) * 32 + lane];  // LDS.128
                        unsigned w0 = (unsigned)wv.x, w1 = (unsigned)(wv.x >> 32);
                        unsigned q0 = (unsigned)wv.y, q1 = (unsigned)(wv.y >> 32);
                        MMA_BF16(acc[G * 3 + nt], ah0, ah1, ah2, ah3, w0, w1);
                        MMA_BF16(acc[G * 3 + nt], al0, al1, al2, al3, w0, w1);
                        MMA_BF16(acc[G * 3 + nt], ah0, ah1, ah2, ah3, q0, q1);
                    }
            }

            // epilogue: activations, c update, h, projection partials
            float2 proj0 = make_float2(0.0f, 0.0f);
            float2 proj1 = make_float2(0.0f, 0.0f);
            #pragma unroll
            for (int nt = 0; nt < 3; nt++) {
                float h[4];
                #pragma unroll
                for (int idx = 0; idx < 4; idx++) {
                    int j = jb + nt * 8 + (idx & 1);
                    float gi = acc[0 * 3 + nt][idx] + biasd[j];
                    float gf = acc[1 * 3 + nt][idx] + biasd[96 + j];
                    float gg = acc[2 * 3 + nt][idx] + biasd[192 + j];
                    float go = acc[3 * 3 + nt][idx] + biasd[288 + j];
                    float fi = sigm(gi);
                    float ff = sigm(gf);
                    float fg = tanh_(gg);
                    float fo = sigm(go);
                    float cn = fmaf(ff, c[nt][idx], fi * fg);
                    c[nt][idx] = cn;
                    h[idx] = fo * tanh_(cn);
                    float2 we = Wemb[j];
                    if (idx < 2) {
                        proj0.x = fmaf(h[idx], we.x, proj0.x);
                        proj0.y = fmaf(h[idx], we.y, proj0.y);
                    } else {
                        proj1.x = fmaf(h[idx], we.x, proj1.x);
                        proj1.y = fmaf(h[idx], we.y, proj1.y);
                    }
                }
                int pidx = (jb >> 1) + nt * 4;
                unsigned ph0, pl0, ph1, pl1;
                split2(h[0], h[1], ph0, pl0);
                split2(h[2], h[3], ph1, pl1);
                HhiN[brow * 49 + pidx] = ph0;        HloN[brow * 49 + pidx] = pl0;
                HhiN[(brow + 8) * 49 + pidx] = ph1;  HloN[(brow + 8) * 49 + pidx] = pl1;
            }
            Ppart[(t & 1) * 1024 + brow * 16 + slot] = proj0;
            Ppart[(t & 1) * 1024 + (brow + 8) * 16 + slot] = proj1;

            __syncthreads();   // new h + partials visible

            // reduce + emit output for step t (64 threads; overlaps next MMAs)
            if (tid < BT) {
                const float4* Pq = (const float4*)(Ppart + (t & 1) * 1024 + tid * 16);
                float2 a = *Bemb;
                #pragma unroll
                for (int q = 0; q < 8; q++) {
                    float4 v = Pq[q];
                    a.x += v.x + v.z;
                    a.y += v.y + v.w;
                }
                int bgl = bbase + tid;
                if (bgl < B) *(float2*)&out[(size_t)(bgl * 30 + t) * 2] = a;
            }
            { unsigned* tp = HhiC; HhiC = HhiN; HhiN = tp; }
            { unsigned* tp = HloC; HloC = HloN; HloN = tp; }
        }
    }
}

extern "C" void kernel_launch(void* const* d_in, const int* in_sizes, int n_in,
                              void* d_out, int out_size)
{
    const float* traj  = (const float*)d_in[0];
    const float* cl    = (const float*)d_in[1];
    const float* Wih_c = (const float*)d_in[2];
    const float* Whh_c = (const float*)d_in[3];
    const float* bih_c = (const float*)d_in[4];
    const float* bhh_c = (const float*)d_in[5];
    const float* Wih_e = (const float*)d_in[6];
    const float* Whh_e = (const float*)d_in[7];
    const float* bih_e = (const float*)d_in[8];
    const float* bhh_e = (const float*)d_in[9];
    const float* Wih_d = (const float*)d_in[10];
    const float* Whh_d = (const float*)d_in[11];
    const float* bih_d = (const float*)d_in[12];
    const float* bhh_d = (const float*)d_in[13];
    const float* W_emb = (const float*)d_in[14];
    const float* b_emb = (const float*)d_in[15];

    int B = in_sizes[0] / 40;
    int grid = (B + BT - 1) / BT;

    cudaFuncSetAttribute(lstm_fused_kernel,
                         cudaFuncAttributeMaxDynamicSharedMemorySize, SMEM_BYTES);
    lstm_fused_kernel<<<grid, TPB, SMEM_BYTES>>>(
        traj, cl, Wih_c, Whh_c, bih_c, bhh_c,
        Wih_e, Whh_e, bih_e, bhh_e,
        Wih_d, Whh_d, bih_d, bhh_d,
        W_emb, b_emb, (float*)d_out, B);
}

// round 16
// speedup vs baseline: 1.1160x; 1.1160x over previous
#include <cuda_runtime.h>
#include <cuda_bf16.h>
#include <cstdint>

typedef unsigned long long ull;

#define TPB  512
#define BT   64

// ---------------- activations (HW tanh, 1 MUFU each) ----------------
__device__ __forceinline__ float tanh_(float x){
    float r; asm("tanh.approx.f32 %0, %1;" : "=f"(r) : "f"(x)); return r;
}
__device__ __forceinline__ float sigm(float x){
    return fmaf(0.5f, tanh_(0.5f * x), 0.5f);
}
// bf16x2 pack: lo half = a, hi half = b
__device__ __forceinline__ unsigned bf16x2_pack(float a, float b) {
    unsigned r;
    asm("cvt.rn.satfinite.bf16x2.f32 %0, %1, %2;" : "=r"(r) : "f"(b), "f"(a));
    return r;
}
// split (a,b) into bf16x2 hi + bf16x2 lo (residual)
__device__ __forceinline__ void split2(float a, float b, unsigned& hi, unsigned& lo) {
    hi = bf16x2_pack(a, b);
    float r0 = __uint_as_float(hi << 16);
    float r1 = __uint_as_float(hi & 0xffff0000u);
    lo = bf16x2_pack(a - r0, b - r1);
}
// mma.sync m16n8k16 row.col f32.bf16.bf16.f32 (baseline PTX, sm_80+)
#define MMA_BF16(d, a0, a1, a2, a3, b0, b1) \
    asm volatile("mma.sync.aligned.m16n8k16.row.col.f32.bf16.bf16.f32 " \
        "{%0,%1,%2,%3}, {%4,%5,%6,%7}, {%8,%9}, {%0,%1,%2,%3};" \
        : "+f"((d)[0]), "+f"((d)[1]), "+f"((d)[2]), "+f"((d)[3]) \
        : "r"(a0), "r"(a1), "r"(a2), "r"(a3), "r"(b0), "r"(b1))

// ---------------- SMEM layout (float offsets) — R13 base + XS ----------------
#define WPC_OFF   0        // cent packed W: 2var x 2kt x 16nt x 32 ull (x-tile removed)
#define WPE_OFF   6144     // enc  packed W: 2var x 5kt x 32nt x 32 ull = 20480 f
#define CS_OFF    26624    // c staging [96][64] = 6144 f
#define PHB_OFF   32768    // phase h buf (hi|lo contiguous), max enc 2*64*40 = 5120 f
#define DHA_HI    37888    // decoder h A hi: 64*49 = 3136 f
#define DHA_LO    41024
#define DHB_HI    44160
#define DHB_LO    47296
#define WPD_OFF   0        // decoder packed W (36864 f) — staged AFTER phases
#define PPART_OFF 50432    // proj partials: 2 x [64][16] float2 = 4096 f
#define BIASD_OFF 54528    // 384 f
#define WEMBD_OFF 54912    // 96 float2
#define BEMBD_OFF 55104    // 1 float2
#define BIASC_OFF 55106    // 128 f
#define BIASE_OFF 55234    // 256 f
#define XS_OFF    55490    // cent x staging: 64 float2 = 128 f
#define SMEM_FLOATS 55618
#define SMEM_BYTES  (SMEM_FLOATS * 4)

// ---------------- phase weight packing ----------------
// XSC=true: only the H/16 h K-tiles (x handled scalar). XSC=false: extra x
// K-tile at kt==KT whose k-local 0,1 hold Wih columns.
template<int H, bool XSC>
__device__ __forceinline__ void stage_Wphase(ull* __restrict__ Wp,
                                             const float* __restrict__ Whh,
                                             const float* __restrict__ Wih, int tid)
{
    constexpr int KT = H / 16, KTX = XSC ? KT : (KT + 1), NT = (4 * H) / 8;
    for (int s = tid; s < KTX * NT * 32; s += TPB) {
        int ln = s & 31;
        int ntile = (s >> 5) % NT;
        int kt = (s >> 5) / NT;
        int n = ntile * 8 + (ln >> 2);
        int kl = (ln & 3) * 2;
        float v00, v01, v10, v11;
        if (kt < KT) {
            const float* r = Whh + n * H + kt * 16 + kl;
            v00 = r[0]; v01 = r[1]; v10 = r[8]; v11 = r[9];
        } else {
            v00 = (kl == 0) ? Wih[n * 2 + 0] : 0.0f;
            v01 = (kl == 0) ? Wih[n * 2 + 1] : 0.0f;
            v10 = 0.0f; v11 = 0.0f;
        }
        unsigned h0, l0, h1, l1;
        split2(v00, v01, h0, l0);
        split2(v10, v11, h1, l1);
        Wp[(kt * NT + ntile) * 32 + ln]         = (ull)h0 | ((ull)h1 << 32);
        Wp[((KTX + kt) * NT + ntile) * 32 + ln] = (ull)l0 | ((ull)l1 << 32);
    }
}

// ---------------- one input-driven LSTM phase via mma.sync (R13 structure) ----
// XSC=true: x contribution via exact scalar fp32 FMAs (Wih in registers,
// x in a small float2 SMEM buffer) — no x K-tile MMAs.
template<int H, int T, bool XSC>
__device__ __forceinline__ void phase_mma(float* __restrict__ S,
                                          const float* __restrict__ xsrc, int xstride,
                                          const float* __restrict__ Wih,
                                          int B, int bbase, int tid,
                                          int wpkOff, int biasOff,
                                          int csHOFF, int dstWordOff)
{
    constexpr int KT  = H / 16;
    constexpr int KTX = XSC ? KT : (KT + 1);
    constexpr int NT  = (4 * H) / 8;
    constexpr int NTG = H / 32;          // j-ntiles per gate per warp
    constexpr int STR = H / 2 + 8;       // words per row (pad; x kt word if !XSC)
    constexpr int BUFW = 64 * STR;

    int w = tid >> 5, lane = tid & 31;
    int mt = w & 3, wg = w >> 2;
    int lq = lane >> 2, lr = lane & 3;
    int brow = mt * 16 + lq;

    unsigned* Hhi = (unsigned*)(S + PHB_OFF);
    unsigned* Hlo = Hhi + BUFW;
    float2*   Xs  = (float2*)(S + XS_OFF);
    const ull* Wp = (const ull*)(S + wpkOff);
    const float* biasPh = S + biasOff;

    // zero buffers (h words start 0; x-kt pad words stay 0 forever)
    for (int s = tid; s < 2 * BUFW; s += TPB) Hhi[s] = 0u;

    // per-thread bias regs
    float bR[4][NTG][2];
    #pragma unroll
    for (int G = 0; G < 4; G++)
        #pragma unroll
        for (int nt = 0; nt < NTG; nt++) {
            int j = (wg * NTG + nt) * 8 + lr * 2;
            bR[G][nt][0] = biasPh[G * H + j];
            bR[G][nt][1] = biasPh[G * H + j + 1];
        }

    // per-thread Wih regs (XSC only): wX[G][nt][p][comp]
    float wX[4][NTG][2][2];
    if (XSC) {
        #pragma unroll
        for (int G = 0; G < 4; G++)
            #pragma unroll
            for (int nt = 0; nt < NTG; nt++)
                #pragma unroll
                for (int p = 0; p < 2; p++) {
                    int j = G * H + (wg * NTG + nt) * 8 + lr * 2 + p;
                    wX[G][nt][p][0] = Wih[j * 2 + 0];
                    wX[G][nt][p][1] = Wih[j * 2 + 1];
                }
    }

    float c[NTG][4];
    #pragma unroll
    for (int nt = 0; nt < NTG; nt++)
        #pragma unroll
        for (int e = 0; e < 4; e++) c[nt][e] = 0.0f;

    int bx = bbase + tid; if (bx >= B) bx = B - 1;
    __syncthreads();                        // zeros done
    if (tid < 64) {                         // stage x(0)
        float2 x = *(const float2*)&xsrc[(size_t)bx * xstride];
        if (XSC) {
            Xs[tid] = x;
        } else {
            unsigned xh, xl; split2(x.x, x.y, xh, xl);
            Hhi[tid * STR + KT * 8] = xh;
            Hlo[tid * STR + KT * 8] = xl;
        }
    }
    __syncthreads();

    int abase = brow * STR + lr;

    for (int t = 0; t < T; t++) {
        float2 xn;
        bool st = (tid < 64) && (t + 1 < T);
        if (st)
            xn = *(const float2*)&xsrc[(size_t)bx * xstride + (size_t)(t + 1) * 2];

        float acc[4 * NTG][4];
        if (XSC) {
            float2 xa = Xs[brow];
            float2 xb = Xs[brow + 8];
            #pragma unroll
            for (int G = 0; G < 4; G++)
                #pragma unroll
                for (int nt = 0; nt < NTG; nt++)
                    #pragma unroll
                    for (int idx = 0; idx < 4; idx++) {
                        float2 xv = (idx & 2) ? xb : xa;
                        int p = idx & 1;
                        acc[G * NTG + nt][idx] =
                            fmaf(xv.y, wX[G][nt][p][1], xv.x * wX[G][nt][p][0]);
                    }
        } else {
            #pragma unroll
            for (int q = 0; q < 4 * NTG; q++)
                #pragma unroll
                for (int e = 0; e < 4; e++) acc[q][e] = 0.0f;
        }

        #pragma unroll
        for (int kt = 0; kt < KTX; kt++) {
            unsigned ah0 = Hhi[abase + kt * 8];
            unsigned ah1 = Hhi[abase + kt * 8 + 8 * STR];
            unsigned ah2 = Hhi[abase + kt * 8 + 4];
            unsigned ah3 = Hhi[abase + kt * 8 + 8 * STR + 4];
            unsigned al0 = Hlo[abase + kt * 8];
            unsigned al1 = Hlo[abase + kt * 8 + 8 * STR];
            unsigned al2 = Hlo[abase + kt * 8 + 4];
            unsigned al3 = Hlo[abase + kt * 8 + 8 * STR + 4];
            #pragma unroll
            for (int G = 0; G < 4; G++)
                #pragma unroll
                for (int nt = 0; nt < NTG; nt++) {
                    int ntile = G * (H / 8) + wg * NTG + nt;
                    ull whi = Wp[(kt * NT + ntile) * 32 + lane];
                    unsigned w0 = (unsigned)whi, w1 = (unsigned)(whi >> 32);
                    MMA_BF16(acc[G * NTG + nt], ah0, ah1, ah2, ah3, w0, w1);
                    MMA_BF16(acc[G * NTG + nt], al0, al1, al2, al3, w0, w1);
                    ull wlo = Wp[((KTX + kt) * NT + ntile) * 32 + lane];
                    unsigned q0 = (unsigned)wlo, q1 = (unsigned)(wlo >> 32);
                    MMA_BF16(acc[G * NTG + nt], ah0, ah1, ah2, ah3, q0, q1);
                }
        }
        __syncthreads();                   // all h/x reads done

        #pragma unroll
        for (int nt = 0; nt < NTG; nt++) {
            float h[4];
            #pragma unroll
            for (int idx = 0; idx < 4; idx++) {
                int p = idx & 1;
                float gi = acc[0 * NTG + nt][idx] + bR[0][nt][p];
                float gf = acc[1 * NTG + nt][idx] + bR[1][nt][p];
                float gg = acc[2 * NTG + nt][idx] + bR[2][nt][p];
                float go = acc[3 * NTG + nt][idx] + bR[3][nt][p];
                float fi = sigm(gi);
                float ff = sigm(gf);
                float fg = tanh_(gg);
                float fo = sigm(go);
                float cn = fmaf(ff, c[nt][idx], fi * fg);
                c[nt][idx] = cn;
                h[idx] = fo * tanh_(cn);
            }
            int jw = (wg * NTG + nt) * 4 + lr;
            unsigned ph0, pl0, ph1, pl1;
            split2(h[0], h[1], ph0, pl0);
            split2(h[2], h[3], ph1, pl1);
            Hhi[brow * STR + jw] = ph0;        Hlo[brow * STR + jw] = pl0;
            Hhi[(brow + 8) * STR + jw] = ph1;  Hlo[(brow + 8) * STR + jw] = pl1;
        }
        if (st) {
            if (XSC) {
                Xs[tid] = xn;
            } else {
                unsigned xh, xl; split2(xn.x, xn.y, xh, xl);
                Hhi[tid * STR + KT * 8] = xh;
                Hlo[tid * STR + KT * 8] = xl;
            }
        }
        __syncthreads();                   // new h + x visible
    }

    // stage final c into Cs
    #pragma unroll
    for (int nt = 0; nt < NTG; nt++)
        #pragma unroll
        for (int idx = 0; idx < 4; idx++) {
            int j = (wg * NTG + nt) * 8 + lr * 2 + (idx & 1);
            int b = brow + (idx >> 1) * 8;
            S[CS_OFF + (csHOFF + j) * 64 + b] = c[nt][idx];
        }

    // copy final h into decoder A buffer (disjoint regions; no race)
    constexpr int CW = 64 * (H / 2);
    unsigned* DHhi = (unsigned*)(S + DHA_HI);
    unsigned* DHlo = (unsigned*)(S + DHA_LO);
    for (int idx = tid; idx < CW; idx += TPB) {
        int row = idx / (H / 2), ww = idx % (H / 2);
        DHhi[row * 49 + dstWordOff + ww] = Hhi[row * STR + ww];
        DHlo[row * 49 + dstWordOff + ww] = Hlo[row * STR + ww];
    }
}

// ---------------- main fused kernel ----------------
__global__ void __launch_bounds__(TPB, 1)
lstm_fused_kernel(const float* __restrict__ traj,   // [B,20,2]
                  const float* __restrict__ cl,     // [B,100,2]
                  const float* __restrict__ Wih_c, const float* __restrict__ Whh_c,
                  const float* __restrict__ bih_c, const float* __restrict__ bhh_c,
                  const float* __restrict__ Wih_e, const float* __restrict__ Whh_e,
                  const float* __restrict__ bih_e, const float* __restrict__ bhh_e,
                  const float* __restrict__ Wih_d, const float* __restrict__ Whh_d,
                  const float* __restrict__ bih_d, const float* __restrict__ bhh_d,
                  const float* __restrict__ W_emb, const float* __restrict__ b_emb,
                  float* __restrict__ out, int B)
{
    extern __shared__ float S[];
    int tid   = threadIdx.x;
    int bbase = blockIdx.x * BT;

    // ---- stage phase weights / biases ----
    stage_Wphase<32, true >((ull*)(S + WPC_OFF), Whh_c, Wih_c, tid);
    stage_Wphase<64, false>((ull*)(S + WPE_OFF), Whh_e, Wih_e, tid);
    for (int j = tid; j < 128; j += TPB) S[BIASC_OFF + j] = bih_c[j] + bhh_c[j];
    for (int j = tid; j < 256; j += TPB) S[BIASE_OFF + j] = bih_e[j] + bhh_e[j];
    __syncthreads();

    // ---- phase 1: centerline (H=32, 100 steps, scalar x) -> dec words 32..47, c rows 64..95
    phase_mma<32, 100, true>(S, cl, 200, Wih_c, B, bbase, tid, WPC_OFF, BIASC_OFF, 64, 32);
    __syncthreads();

    // ---- phase 2: encoder (H=64, 20 steps, x K-tile) -> dec words 0..31, c rows 0..63
    phase_mma<64, 20, false>(S, traj, 40, Wih_e, B, bbase, tid, WPE_OFF, BIASE_OFF, 0, 0);
    __syncthreads();

    // ================= decoder via mma.sync (split-bf16) — R13 verbatim ======
    {
        int w    = tid >> 5, lane = tid & 31;
        int mt   = w & 3;
        int wg   = w >> 2;
        int lq   = lane >> 2;
        int lr   = lane & 3;
        int brow = mt * 16 + lq;
        int jb   = wg * 24 + lr * 2;

        // read c (D-frag layout) BEFORE decoder W staging clobbers Cs
        float c[3][4];
        #pragma unroll
        for (int nt = 0; nt < 3; nt++)
            #pragma unroll
            for (int idx = 0; idx < 4; idx++) {
                int j = jb + nt * 8 + (idx & 1);
                int b = brow + (idx >> 1) * 8;
                c[nt][idx] = S[CS_OFF + j * 64 + b];
            }
        __syncthreads();

        // stage frag-packed decoder W (hi/lo), bias, Wemb
        ull* Wp = (ull*)(S + WPD_OFF);
        for (int s = tid; s < 6 * 48 * 32; s += TPB) {
            int ln = s & 31;
            int ntile = (s >> 5) % 48;
            int kt = (s >> 5) / 48;
            int n  = ntile * 8 + (ln >> 2);
            int k0 = kt * 16 + (ln & 3) * 2;
            const float* wi = Wih_d + n * 96;
            const float* wh = Whh_d + n * 96;
            float v00 = wi[k0]     + wh[k0];
            float v01 = wi[k0 + 1] + wh[k0 + 1];
            float v10 = wi[k0 + 8] + wh[k0 + 8];
            float v11 = wi[k0 + 9] + wh[k0 + 9];
            unsigned h0, l0, h1, l1;
            split2(v00, v01, h0, l0);
            split2(v10, v11, h1, l1);
            Wp[(kt * 48 + ntile) * 32 + ln]       = (ull)h0 | ((ull)h1 << 32);
            Wp[((6 + kt) * 48 + ntile) * 32 + ln] = (ull)l0 | ((ull)l1 << 32);
        }
        float* biasd = S + BIASD_OFF;
        for (int j = tid; j < 384; j += TPB) biasd[j] = bih_d[j] + bhh_d[j];
        float2* Wemb = (float2*)(S + WEMBD_OFF);
        for (int k = tid; k < 96; k += TPB) Wemb[k] = make_float2(W_emb[k], W_emb[96 + k]);
        float2* Bemb = (float2*)(S + BEMBD_OFF);
        if (tid == 0) *Bemb = make_float2(b_emb[0], b_emb[1]);
        __syncthreads();

        unsigned* HhiC = (unsigned*)(S + DHA_HI);
        unsigned* HloC = (unsigned*)(S + DHA_LO);
        unsigned* HhiN = (unsigned*)(S + DHB_HI);
        unsigned* HloN = (unsigned*)(S + DHB_LO);
        float2* Ppart = (float2*)(S + PPART_OFF);   // [2 par][64 b][16 slot]
        int slot = wg * 4 + lr;
        int abase = brow * 49 + lr;

        for (int t = 0; t < 30; t++) {
            float acc[12][4];
            #pragma unroll
            for (int q = 0; q < 12; q++)
                #pragma unroll
                for (int e = 0; e < 4; e++) acc[q][e] = 0.0f;

            #pragma unroll
            for (int kt = 0; kt < 6; kt++) {
                unsigned ah0 = HhiC[abase + kt * 8];
                unsigned ah1 = HhiC[abase + kt * 8 + 392];
                unsigned ah2 = HhiC[abase + kt * 8 + 4];
                unsigned ah3 = HhiC[abase + kt * 8 + 396];
                unsigned al0 = HloC[abase + kt * 8];
                unsigned al1 = HloC[abase + kt * 8 + 392];
                unsigned al2 = HloC[abase + kt * 8 + 4];
                unsigned al3 = HloC[abase + kt * 8 + 396];
                #pragma unroll
                for (int G = 0; G < 4; G++)
                    #pragma unroll
                    for (int nt = 0; nt < 3; nt++) {
                        int ntile = G * 12 + wg * 3 + nt;
                        ull whi = Wp[(kt * 48 + ntile) * 32 + lane];
                        unsigned w0 = (unsigned)whi, w1 = (unsigned)(whi >> 32);
                        MMA_BF16(acc[G * 3 + nt], ah0, ah1, ah2, ah3, w0, w1);
                        MMA_BF16(acc[G * 3 + nt], al0, al1, al2, al3, w0, w1);
                        ull wlo = Wp[((6 + kt) * 48 + ntile) * 32 + lane];
                        unsigned q0 = (unsigned)wlo, q1 = (unsigned)(wlo >> 32);
                        MMA_BF16(acc[G * 3 + nt], ah0, ah1, ah2, ah3, q0, q1);
                    }
            }

            // epilogue: activations, c update, h, projection partials
            float2 proj0 = make_float2(0.0f, 0.0f);
            float2 proj1 = make_float2(0.0f, 0.0f);
            #pragma unroll
            for (int nt = 0; nt < 3; nt++) {
                float h[4];
                #pragma unroll
                for (int idx = 0; idx < 4; idx++) {
                    int j = jb + nt * 8 + (idx & 1);
                    float gi = acc[0 * 3 + nt][idx] + biasd[j];
                    float gf = acc[1 * 3 + nt][idx] + biasd[96 + j];
                    float gg = acc[2 * 3 + nt][idx] + biasd[192 + j];
                    float go = acc[3 * 3 + nt][idx] + biasd[288 + j];
                    float fi = sigm(gi);
                    float ff = sigm(gf);
                    float fg = tanh_(gg);
                    float fo = sigm(go);
                    float cn = fmaf(ff, c[nt][idx], fi * fg);
                    c[nt][idx] = cn;
                    h[idx] = fo * tanh_(cn);
                    float2 we = Wemb[j];
                    if (idx < 2) {
                        proj0.x = fmaf(h[idx], we.x, proj0.x);
                        proj0.y = fmaf(h[idx], we.y, proj0.y);
                    } else {
                        proj1.x = fmaf(h[idx], we.x, proj1.x);
                        proj1.y = fmaf(h[idx], we.y, proj1.y);
                    }
                }
                int pidx = (jb >> 1) + nt * 4;
                unsigned ph0, pl0, ph1, pl1;
                split2(h[0], h[1], ph0, pl0);
                split2(h[2], h[3], ph1, pl1);
                HhiN[brow * 49 + pidx] = ph0;        HloN[brow * 49 + pidx] = pl0;
                HhiN[(brow + 8) * 49 + pidx] = ph1;  HloN[(brow + 8) * 49 + pidx] = pl1;
            }
            Ppart[(t & 1) * 1024 + brow * 16 + slot] = proj0;
            Ppart[(t & 1) * 1024 + (brow + 8) * 16 + slot] = proj1;

            __syncthreads();   // new h + partials visible

            // reduce + emit output for step t (64 threads; overlaps next MMAs)
            if (tid < BT) {
                const float4* Pq = (const float4*)(Ppart + (t & 1) * 1024 + tid * 16);
                float2 a = *Bemb;
                #pragma unroll
                for (int q = 0; q < 8; q++) {
                    float4 v = Pq[q];
                    a.x += v.x + v.z;
                    a.y += v.y + v.w;
                }
                int bgl = bbase + tid;
                if (bgl < B) *(float2*)&out[(size_t)(bgl * 30 + t) * 2] = a;
            }
            { unsigned* tp = HhiC; HhiC = HhiN; HhiN = tp; }
            { unsigned* tp = HloC; HloC = HloN; HloN = tp; }
        }
    }
}

extern "C" void kernel_launch(void* const* d_in, const int* in_sizes, int n_in,
                              void* d_out, int out_size)
{
    const float* traj  = (const float*)d_in[0];
    const float* cl    = (const float*)d_in[1];
    const float* Wih_c = (const float*)d_in[2];
    const float* Whh_c = (const float*)d_in[3];
    const float* bih_c = (const float*)d_in[4];
    const float* bhh_c = (const float*)d_in[5];
    const float* Wih_e = (const float*)d_in[6];
    const float* Whh_e = (const float*)d_in[7];
    const float* bih_e = (const float*)d_in[8];
    const float* bhh_e = (const float*)d_in[9];
    const float* Wih_d = (const float*)d_in[10];
    const float* Whh_d = (const float*)d_in[11];
    const float* bih_d = (const float*)d_in[12];
    const float* bhh_d = (const float*)d_in[13];
    const float* W_emb = (const float*)d_in[14];
    const float* b_emb = (const float*)d_in[15];

    int B = in_sizes[0] / 40;
    int grid = (B + BT - 1) / BT;

    cudaFuncSetAttribute(lstm_fused_kernel,
                         cudaFuncAttributeMaxDynamicSharedMemorySize, SMEM_BYTES);
    lstm_fused_kernel<<<grid, TPB, SMEM_BYTES>>>(
        traj, cl, Wih_c, Whh_c, bih_c, bhh_c,
        Wih_e, Whh_e, bih_e, bhh_e,
        Wih_d, Whh_d, bih_d, bhh_d,
        W_emb, b_emb, (float*)d_out, B);
}